// round 6
// baseline (speedup 1.0000x reference)
#include <cuda_runtime.h>
#include <cuda_bf16.h>
#include <mma.h>

using namespace nvcuda;

#define B_  4
#define S_  2048
#define E_  1024
#define H_  16
#define DH_ 64
#define BS_ (B_*S_)   // 8192

// Scratch (allocation-free rule: __device__ globals)
__device__ float g_q[H_*BS_*DH_];       // Q pre-scaled by 1/8
__device__ float g_k[H_*BS_*DH_];
__device__ float g_v[H_*BS_*DH_];
__device__ float g_concat[BS_*E_];      // [b,s, h*64+d]
__device__ float g_invl[H_*BS_];        // per-row 1/l

typedef wmma::fragment<wmma::matrix_a, 16,16,8, wmma::precision::tf32, wmma::row_major> FragA;
typedef wmma::fragment<wmma::matrix_b, 16,16,8, wmma::precision::tf32, wmma::col_major> FragBc;
typedef wmma::fragment<wmma::matrix_b, 16,16,8, wmma::precision::tf32, wmma::row_major> FragBr;
typedef wmma::fragment<wmma::accumulator, 16,16,8, float> FragC;

__device__ __forceinline__ float4 tf4(float4 v) {
    v.x = wmma::__float_to_tf32(v.x);
    v.y = wmma::__float_to_tf32(v.y);
    v.z = wmma::__float_to_tf32(v.z);
    v.w = wmma::__float_to_tf32(v.w);
    return v;
}

// ---------------------------------------------------------------------------
// K1: fused QKV projection.  Tile 128(m) x 64(n=DH), K-chunk 32.
// 8 warps as 4(m) x 2(n), warp tile 32x32 (4 C frags).
// grid (BS/128, H, 3), block 256.
// ---------------------------------------------------------------------------
__global__ void qkv_tc_kernel(const float* __restrict__ hs,
                              const float* __restrict__ Wq, const float* __restrict__ bq,
                              const float* __restrict__ Wk, const float* __restrict__ bk,
                              const float* __restrict__ Wv, const float* __restrict__ bv) {
    const int h = blockIdx.y;
    const float* W; const float* bias; float* out; float out_scale;
    if (blockIdx.z == 0)      { W = Wq; bias = bq; out = g_q; out_scale = 0.125f; }
    else if (blockIdx.z == 1) { W = Wk; bias = bk; out = g_k; out_scale = 1.0f; }
    else                      { W = Wv; bias = bv; out = g_v; out_scale = 1.0f; }
    W    += (size_t)h * E_ * DH_;
    bias += h * DH_;
    out  += (size_t)h * BS_ * DH_;

    __shared__ float sm[128*68];                     // 34.8 KB
    float (*As)[36] = (float(*)[36])sm;              // 128 x 32 (+pad)
    float (*Bs)[68] = (float(*)[68])(sm + 128*36);   // 32 x 64 (+pad)
    float (*St)[68] = (float(*)[68])sm;              // 128 x 64 stage (aliases)

    const int tid  = threadIdx.x;
    const int warp = tid >> 5;
    const int wm = warp >> 1, wn = warp & 1;         // m: wm*32, n: wn*32
    const int m0 = blockIdx.x * 128;

    FragC c00, c01, c10, c11;
    wmma::fill_fragment(c00, 0.f); wmma::fill_fragment(c01, 0.f);
    wmma::fill_fragment(c10, 0.f); wmma::fill_fragment(c11, 0.f);

    for (int k0 = 0; k0 < E_; k0 += 32) {
        #pragma unroll
        for (int i = 0; i < 4; i++) {                // As: 1024 float4
            const int vi = tid + i * 256;
            const int r = vi >> 3, c = (vi & 7) * 4;
            *(float4*)&As[r][c] = tf4(*(const float4*)&hs[(size_t)(m0 + r) * E_ + k0 + c]);
        }
        #pragma unroll
        for (int i = 0; i < 2; i++) {                // Bs: 512 float4
            const int vi = tid + i * 256;
            const int r = vi >> 4, c = (vi & 15) * 4;
            *(float4*)&Bs[r][c] = tf4(*(const float4*)&W[(size_t)(k0 + r) * DH_ + c]);
        }
        __syncthreads();
        #pragma unroll
        for (int kk = 0; kk < 32; kk += 8) {
            FragA a0, a1; FragBr b0, b1;
            wmma::load_matrix_sync(a0, &As[wm*32][kk], 36);
            wmma::load_matrix_sync(a1, &As[wm*32 + 16][kk], 36);
            wmma::load_matrix_sync(b0, &Bs[kk][wn*32], 68);
            wmma::load_matrix_sync(b1, &Bs[kk][wn*32 + 16], 68);
            wmma::mma_sync(c00, a0, b0, c00);
            wmma::mma_sync(c01, a0, b1, c01);
            wmma::mma_sync(c10, a1, b0, c10);
            wmma::mma_sync(c11, a1, b1, c11);
        }
        __syncthreads();
    }
    wmma::store_matrix_sync(&St[wm*32][wn*32],           c00, 68, wmma::mem_row_major);
    wmma::store_matrix_sync(&St[wm*32][wn*32 + 16],      c01, 68, wmma::mem_row_major);
    wmma::store_matrix_sync(&St[wm*32 + 16][wn*32],      c10, 68, wmma::mem_row_major);
    wmma::store_matrix_sync(&St[wm*32 + 16][wn*32 + 16], c11, 68, wmma::mem_row_major);
    __syncthreads();
    #pragma unroll
    for (int i = 0; i < 8; i++) {                    // out: 2048 float4
        const int vi = tid + i * 256;
        const int r = vi >> 4, c = (vi & 15) * 4;
        float4 s = *(float4*)&St[r][c];
        s.x = (s.x + bias[c])   * out_scale;
        s.y = (s.y + bias[c+1]) * out_scale;
        s.z = (s.z + bias[c+2]) * out_scale;
        s.w = (s.w + bias[c+3]) * out_scale;
        *(float4*)&out[(size_t)(m0 + r) * DH_ + c] = s;
    }
}

// ---------------------------------------------------------------------------
// K2: single-pass attention, deferred normalization.  M-tile 64, KV-tile 64.
// Dynamic smem: region0 (Qs -> Ss -> stage) + Ks + Vs, each 64x68.
// grid (S/64, H*B), block 256 (8 warps: 4m x 2n, warp 16x32).
// ---------------------------------------------------------------------------
__global__ void attn_fused_kernel(float* __restrict__ wts) {
    const int hb = blockIdx.y;
    const int h = hb / B_, b = hb % B_;
    const int m0 = blockIdx.x * 64;
    const float* q = g_q + ((size_t)h * BS_ + (size_t)b * S_) * DH_;
    const float* k = g_k + ((size_t)h * BS_ + (size_t)b * S_) * DH_;
    const float* v = g_v + ((size_t)h * BS_ + (size_t)b * S_) * DH_;
    float* w = wts + (size_t)hb * S_ * S_;

    extern __shared__ float smd[];
    float (*Qs)[68] = (float(*)[68])smd;               // 64x68; later Ss, later stage
    float (*Ss)[68] = Qs;
    float (*Ks)[68] = (float(*)[68])(smd + 64*68);
    float (*Vs)[68] = (float(*)[68])(smd + 2*64*68);
    __shared__ float l_s[64];

    const int tid  = threadIdx.x;
    const int warp = tid >> 5;
    const int wm = warp >> 1, wn = warp & 1;

    // load Q tile (pre-scaled by 1/8), rounded to tf32
    #pragma unroll
    for (int i = 0; i < 4; i++) {
        const int vi = tid + i * 256;
        const int r = vi >> 4, c = (vi & 15) * 4;
        *(float4*)&Qs[r][c] = tf4(*(const float4*)&q[(size_t)(m0 + r) * DH_ + c]);
    }
    __syncthreads();

    FragA qa[8];
    #pragma unroll
    for (int kk = 0; kk < 8; kk++)
        wmma::load_matrix_sync(qa[kk], &Qs[wm*16][kk*8], 68);
    __syncthreads();   // Qs free -> becomes Ss

    const int row = tid >> 2, qd = tid & 3;   // 64 rows x 4 lanes (16 cols each)
    float lsum = 0.f;

    FragC pv0, pv1;
    wmma::fill_fragment(pv0, 0.f);
    wmma::fill_fragment(pv1, 0.f);

    for (int t0 = 0; t0 < S_; t0 += 64) {
        #pragma unroll
        for (int i = 0; i < 4; i++) {
            const int vi = tid + i * 256;
            const int r = vi >> 4, c = (vi & 15) * 4;
            *(float4*)&Ks[r][c] = tf4(*(const float4*)&k[(size_t)(t0 + r) * DH_ + c]);
            *(float4*)&Vs[r][c] = tf4(*(const float4*)&v[(size_t)(t0 + r) * DH_ + c]);
        }
        __syncthreads();

        // QK^T: out 64x64, warp 16x32
        FragC c0, c1;
        wmma::fill_fragment(c0, 0.f);
        wmma::fill_fragment(c1, 0.f);
        #pragma unroll
        for (int kk = 0; kk < 8; kk++) {
            FragBc b0, b1;
            wmma::load_matrix_sync(b0, &Ks[wn*32][kk*8], 68);
            wmma::load_matrix_sync(b1, &Ks[wn*32 + 16][kk*8], 68);
            wmma::mma_sync(c0, qa[kk], b0, c0);
            wmma::mma_sync(c1, qa[kk], b1, c1);
        }
        wmma::store_matrix_sync(&Ss[wm*16][wn*32],      c0, 68, wmma::mem_row_major);
        wmma::store_matrix_sync(&Ss[wm*16][wn*32 + 16], c1, 68, wmma::mem_row_major);
        __syncthreads();

        // exp, accumulate l, write unnormalized P to gmem, rounded P to smem
        {
            float* wr = &w[(size_t)(m0 + row) * S_ + t0 + qd*16];
            #pragma unroll
            for (int jj = 0; jj < 4; jj++) {
                float4 sv = *(float4*)&Ss[row][qd*16 + jj*4];
                sv.x = __expf(sv.x); sv.y = __expf(sv.y);
                sv.z = __expf(sv.z); sv.w = __expf(sv.w);
                lsum += sv.x + sv.y + sv.z + sv.w;
                *(float4*)(wr + jj*4) = sv;
                *(float4*)&Ss[row][qd*16 + jj*4] = tf4(sv);
            }
        }
        __syncthreads();

        // PV accumulate: attn[64,64] += P[64,64] @ V[64,64]
        #pragma unroll
        for (int kk = 0; kk < 64; kk += 8) {
            FragA a; wmma::load_matrix_sync(a, &Ss[wm*16][kk], 68);
            FragBr b0, b1;
            wmma::load_matrix_sync(b0, &Vs[kk][wn*32], 68);
            wmma::load_matrix_sync(b1, &Vs[kk][wn*32 + 16], 68);
            wmma::mma_sync(pv0, a, b0, pv0);
            wmma::mma_sync(pv1, a, b1, pv1);
        }
        __syncthreads();
    }

    // finalize 1/l per row (4 lanes of a row are consecutive)
    lsum += __shfl_xor_sync(0xffffffffu, lsum, 1);
    lsum += __shfl_xor_sync(0xffffffffu, lsum, 2);
    const float inv = 1.0f / lsum;
    if (qd == 0) {
        l_s[row] = inv;
        g_invl[(size_t)hb * S_ + m0 + row] = inv;
    }

    // stage PV, scale rows by 1/l, write concat layout [b, s, h*64 + d]
    wmma::store_matrix_sync(&Ss[wm*16][wn*32],      pv0, 68, wmma::mem_row_major);
    wmma::store_matrix_sync(&Ss[wm*16][wn*32 + 16], pv1, 68, wmma::mem_row_major);
    __syncthreads();
    #pragma unroll
    for (int i = 0; i < 4; i++) {
        const int vi = tid + i * 256;
        const int r = vi >> 4, c = (vi & 15) * 4;
        const float il = l_s[r];
        float4 s = *(float4*)&Ss[r][c];
        s.x *= il; s.y *= il; s.z *= il; s.w *= il;
        *(float4*)&g_concat[((size_t)(b * S_ + m0 + r)) * E_ + h * DH_ + c] = s;
    }
}

// ---------------------------------------------------------------------------
// K3: rescale weights in place by 1/l and accumulate electrode.
// grid (2, H*B, 4), block 256.  Each thread: 4 columns (float4), 512 rows.
// ---------------------------------------------------------------------------
__global__ void rescale_kernel(float* __restrict__ wts, float* __restrict__ elect) {
    const int hb = blockIdx.y;
    const int b = hb % B_;
    const int t = (blockIdx.x * 256 + threadIdx.x) * 4;
    const int s0 = blockIdx.z * 512;

    __shared__ float il[512];
    #pragma unroll
    for (int i = threadIdx.x; i < 512; i += 256)
        il[i] = g_invl[(size_t)hb * S_ + s0 + i];
    __syncthreads();

    float* wp = wts + (size_t)hb * S_ * S_ + (size_t)s0 * S_ + t;
    float4 acc = make_float4(0.f, 0.f, 0.f, 0.f);
    #pragma unroll 4
    for (int s = 0; s < 512; s++) {
        float4 vv = *(float4*)(wp + (size_t)s * S_);
        const float f = il[s];
        vv.x *= f; vv.y *= f; vv.z *= f; vv.w *= f;
        *(float4*)(wp + (size_t)s * S_) = vv;
        acc.x += vv.x; acc.y += vv.y; acc.z += vv.z; acc.w += vv.w;
    }
    const float sc = 1.0f / (H_ * S_);
    atomicAdd(&elect[b * S_ + t],     acc.x * sc);
    atomicAdd(&elect[b * S_ + t + 1], acc.y * sc);
    atomicAdd(&elect[b * S_ + t + 2], acc.z * sc);
    atomicAdd(&elect[b * S_ + t + 3], acc.w * sc);
}

// ---------------------------------------------------------------------------
// K4: O-projection.  Tile 128(m) x 64(n), K-chunk 32, warp 32x32.
// x[m,n] = sum_k concat[m,k]*Wo[n,k] + bo[n].  grid (E/64, BS/128), block 256.
// ---------------------------------------------------------------------------
__global__ void oproj_tc_kernel(const float* __restrict__ Wo, const float* __restrict__ bo,
                                float* __restrict__ x) {
    const int n0 = blockIdx.x * 64, m0 = blockIdx.y * 128;

    __shared__ float sm[128*68];
    float (*As)[36] = (float(*)[36])sm;              // 128 x 32
    float (*Bs)[36] = (float(*)[36])(sm + 128*36);   // 64(n) x 32(k)
    float (*St)[68] = (float(*)[68])sm;              // stage

    const int tid  = threadIdx.x;
    const int warp = tid >> 5;
    const int wm = warp >> 1, wn = warp & 1;

    FragC c00, c01, c10, c11;
    wmma::fill_fragment(c00, 0.f); wmma::fill_fragment(c01, 0.f);
    wmma::fill_fragment(c10, 0.f); wmma::fill_fragment(c11, 0.f);

    for (int k0 = 0; k0 < E_; k0 += 32) {
        #pragma unroll
        for (int i = 0; i < 4; i++) {                // As: 1024 float4
            const int vi = tid + i * 256;
            const int r = vi >> 3, c = (vi & 7) * 4;
            *(float4*)&As[r][c] = tf4(*(const float4*)&g_concat[(size_t)(m0 + r) * E_ + k0 + c]);
        }
        #pragma unroll
        for (int i = 0; i < 2; i++) {                // Bs: 512 float4
            const int vi = tid + i * 256;
            const int r = vi >> 3, c = (vi & 7) * 4;
            *(float4*)&Bs[r][c] = tf4(*(const float4*)&Wo[(size_t)(n0 + r) * E_ + k0 + c]);
        }
        __syncthreads();
        #pragma unroll
        for (int kk = 0; kk < 32; kk += 8) {
            FragA a0, a1; FragBc b0, b1;
            wmma::load_matrix_sync(a0, &As[wm*32][kk], 36);
            wmma::load_matrix_sync(a1, &As[wm*32 + 16][kk], 36);
            wmma::load_matrix_sync(b0, &Bs[wn*32][kk], 36);
            wmma::load_matrix_sync(b1, &Bs[wn*32 + 16][kk], 36);
            wmma::mma_sync(c00, a0, b0, c00);
            wmma::mma_sync(c01, a0, b1, c01);
            wmma::mma_sync(c10, a1, b0, c10);
            wmma::mma_sync(c11, a1, b1, c11);
        }
        __syncthreads();
    }
    wmma::store_matrix_sync(&St[wm*32][wn*32],           c00, 68, wmma::mem_row_major);
    wmma::store_matrix_sync(&St[wm*32][wn*32 + 16],      c01, 68, wmma::mem_row_major);
    wmma::store_matrix_sync(&St[wm*32 + 16][wn*32],      c10, 68, wmma::mem_row_major);
    wmma::store_matrix_sync(&St[wm*32 + 16][wn*32 + 16], c11, 68, wmma::mem_row_major);
    __syncthreads();
    #pragma unroll
    for (int i = 0; i < 8; i++) {
        const int vi = tid + i * 256;
        const int r = vi >> 4, c = (vi & 15) * 4;
        float4 s = *(float4*)&St[r][c];
        s.x += bo[n0 + c]; s.y += bo[n0 + c + 1]; s.z += bo[n0 + c + 2]; s.w += bo[n0 + c + 3];
        *(float4*)&x[(size_t)(m0 + r) * E_ + n0 + c] = s;
    }
}

// ---------------------------------------------------------------------------
__global__ void zero_elect_kernel(float* __restrict__ elect) {
    const int i = blockIdx.x * blockDim.x + threadIdx.x;
    if (i < B_ * S_) elect[i] = 0.f;
}

// ---------------------------------------------------------------------------
extern "C" void kernel_launch(void* const* d_in, const int* in_sizes, int n_in,
                              void* d_out, int out_size) {
    const float* hs = (const float*)d_in[0];
    const float* Wq = (const float*)d_in[1];
    const float* bq = (const float*)d_in[2];
    const float* Wk = (const float*)d_in[3];
    const float* bk = (const float*)d_in[4];
    const float* Wv = (const float*)d_in[5];
    const float* bv = (const float*)d_in[6];
    const float* Wo = (const float*)d_in[7];
    const float* bo = (const float*)d_in[8];

    float* out   = (float*)d_out;
    float* x     = out;                                        // [B,S,E]
    float* wts   = out + (size_t)B_ * S_ * E_;                 // [H,B,S,S]
    float* elect = wts + (size_t)H_ * B_ * S_ * S_;            // [B,S]

    const int attn_smem = 3 * 64 * 68 * sizeof(float);         // 52.2 KB
    cudaFuncSetAttribute(attn_fused_kernel,
                         cudaFuncAttributeMaxDynamicSharedMemorySize, attn_smem);

    zero_elect_kernel<<<(B_*S_ + 255)/256, 256>>>(elect);
    qkv_tc_kernel<<<dim3(BS_/128, H_, 3), 256>>>(hs, Wq, bq, Wk, bk, Wv, bv);
    attn_fused_kernel<<<dim3(S_/64, H_*B_), 256, attn_smem>>>(wts);
    rescale_kernel<<<dim3(2, H_*B_, 4), 256>>>(wts, elect);
    oproj_tc_kernel<<<dim3(E_/64, BS_/128), 256>>>(Wo, bo, x);
}

// round 9
// speedup vs baseline: 1.1836x; 1.1836x over previous
#include <cuda_runtime.h>
#include <cuda_bf16.h>
#include <mma.h>

using namespace nvcuda;

#define B_  4
#define S_  2048
#define E_  1024
#define H_  16
#define DH_ 64
#define BS_ (B_*S_)   // 8192

// Scratch (allocation-free rule: __device__ globals)
__device__ float g_q[H_*BS_*DH_];       // Q pre-scaled by 1/8
__device__ float g_k[H_*BS_*DH_];
__device__ float g_v[H_*BS_*DH_];
__device__ float g_concat[BS_*E_];      // [b,s, h*64+d]
__device__ float g_invl[H_*BS_];        // per-row 1/l

typedef wmma::fragment<wmma::matrix_a, 16,16,8, wmma::precision::tf32, wmma::row_major> FragA;
typedef wmma::fragment<wmma::matrix_b, 16,16,8, wmma::precision::tf32, wmma::col_major> FragBc;
typedef wmma::fragment<wmma::matrix_b, 16,16,8, wmma::precision::tf32, wmma::row_major> FragBr;
typedef wmma::fragment<wmma::accumulator, 16,16,8, float> FragC;

__device__ __forceinline__ float4 tf4(float4 v) {
    v.x = wmma::__float_to_tf32(v.x);
    v.y = wmma::__float_to_tf32(v.y);
    v.z = wmma::__float_to_tf32(v.z);
    v.w = wmma::__float_to_tf32(v.w);
    return v;
}

// ---------------------------------------------------------------------------
// K1: fused QKV projection (tf32, tiles pre-rounded -> no per-fragment CVT).
// out[h,m,d] = (sum_e hs[m,e]*W[h,e,d] + b[h,d]) * out_scale
// grid (BS/64, H, 3), block 256.  Tile 64x64, K-chunk 64.
// ---------------------------------------------------------------------------
__global__ void qkv_tc_kernel(const float* __restrict__ hs,
                              const float* __restrict__ Wq, const float* __restrict__ bq,
                              const float* __restrict__ Wk, const float* __restrict__ bk,
                              const float* __restrict__ Wv, const float* __restrict__ bv) {
    const int h = blockIdx.y;
    const float* W; const float* bias; float* out; float out_scale;
    if (blockIdx.z == 0)      { W = Wq; bias = bq; out = g_q; out_scale = 0.125f; }
    else if (blockIdx.z == 1) { W = Wk; bias = bk; out = g_k; out_scale = 1.0f; }
    else                      { W = Wv; bias = bv; out = g_v; out_scale = 1.0f; }
    W    += (size_t)h * E_ * DH_;
    bias += h * DH_;
    out  += (size_t)h * BS_ * DH_;

    __shared__ float As[64][68];
    __shared__ float Bs[64][68];
    float (*St)[68] = As;   // epilogue stage aliases As

    const int tid  = threadIdx.x;
    const int warp = tid >> 5;
    const int wm = warp >> 1, wn = warp & 1;
    const int m0 = blockIdx.x * 64;

    FragC c0, c1;
    wmma::fill_fragment(c0, 0.f);
    wmma::fill_fragment(c1, 0.f);

    for (int k0 = 0; k0 < E_; k0 += 64) {
        #pragma unroll
        for (int i = 0; i < 4; i++) {
            const int vi = tid + i * 256;
            const int r = vi >> 4, c = (vi & 15) * 4;
            *(float4*)&As[r][c] = tf4(*(const float4*)&hs[(size_t)(m0 + r) * E_ + k0 + c]);
            *(float4*)&Bs[r][c] = tf4(*(const float4*)&W[(size_t)(k0 + r) * DH_ + c]);
        }
        __syncthreads();
        #pragma unroll
        for (int kk = 0; kk < 64; kk += 8) {
            FragA a; wmma::load_matrix_sync(a, &As[wm*16][kk], 68);
            FragBr b0; wmma::load_matrix_sync(b0, &Bs[kk][wn*32], 68);
            wmma::mma_sync(c0, a, b0, c0);
            FragBr b1; wmma::load_matrix_sync(b1, &Bs[kk][wn*32 + 16], 68);
            wmma::mma_sync(c1, a, b1, c1);
        }
        __syncthreads();
    }
    wmma::store_matrix_sync(&St[wm*16][wn*32],      c0, 68, wmma::mem_row_major);
    wmma::store_matrix_sync(&St[wm*16][wn*32 + 16], c1, 68, wmma::mem_row_major);
    __syncthreads();
    #pragma unroll
    for (int i = 0; i < 4; i++) {
        const int vi = tid + i * 256;
        const int r = vi >> 4, c = (vi & 15) * 4;
        float4 s = *(float4*)&St[r][c];
        s.x = (s.x + bias[c])   * out_scale;
        s.y = (s.y + bias[c+1]) * out_scale;
        s.z = (s.z + bias[c+2]) * out_scale;
        s.w = (s.w + bias[c+3]) * out_scale;
        *(float4*)&out[(size_t)(m0 + r) * DH_ + c] = s;
    }
}

// ---------------------------------------------------------------------------
// K2: single-pass attention (deferred normalization).
// Per block: 64 query rows of one (h,b).  Streams KV in tiles of 32.
// Writes UNNORMALIZED exp(S) to weights, accumulates l in registers,
// accumulates PV unnormalized, scales by 1/l at epilogue, stores 1/l.
// ---------------------------------------------------------------------------
__global__ void attn_fused_kernel(float* __restrict__ wts) {
    const int hb = blockIdx.y;
    const int h = hb / B_, b = hb % B_;
    const int m0 = blockIdx.x * 64;
    const float* q = g_q + ((size_t)h * BS_ + (size_t)b * S_) * DH_;
    const float* k = g_k + ((size_t)h * BS_ + (size_t)b * S_) * DH_;
    const float* v = g_v + ((size_t)h * BS_ + (size_t)b * S_) * DH_;
    float* w = wts + (size_t)hb * S_ * S_;

    __shared__ float Qs[64][68];     // also epilogue stage
    __shared__ float Ks[32][68];
    __shared__ float Vs[32][68];
    __shared__ float Ss[64][36];
    __shared__ float l_s[64];

    const int tid  = threadIdx.x;
    const int warp = tid >> 5;
    const int wm = warp >> 1, wn = warp & 1;

    // load Q tile (already scaled by 1/8), pre-rounded to tf32
    #pragma unroll
    for (int i = 0; i < 4; i++) {
        const int vi = tid + i * 256;
        const int r = vi >> 4, c = (vi & 15) * 4;
        *(float4*)&Qs[r][c] = tf4(*(const float4*)&q[(size_t)(m0 + r) * DH_ + c]);
    }
    __syncthreads();

    FragA qa[8];
    #pragma unroll
    for (int kk = 0; kk < 8; kk++)
        wmma::load_matrix_sync(qa[kk], &Qs[wm*16][kk*8], 68);

    const int row = tid >> 2, qd = tid & 3;   // 64 rows x 4 lanes
    float lsum = 0.f;

    FragC pv0, pv1;
    wmma::fill_fragment(pv0, 0.f);
    wmma::fill_fragment(pv1, 0.f);

    for (int t0 = 0; t0 < S_; t0 += 32) {
        #pragma unroll
        for (int i = 0; i < 2; i++) {
            const int vi = tid + i * 256;
            const int r = vi >> 4, c = (vi & 15) * 4;
            *(float4*)&Ks[r][c] = tf4(*(const float4*)&k[(size_t)(t0 + r) * DH_ + c]);
            *(float4*)&Vs[r][c] = tf4(*(const float4*)&v[(size_t)(t0 + r) * DH_ + c]);
        }
        __syncthreads();

        FragC c0;
        wmma::fill_fragment(c0, 0.f);
        #pragma unroll
        for (int kk = 0; kk < 8; kk++) {
            FragBc bb; wmma::load_matrix_sync(bb, &Ks[wn*16][kk*8], 68);
            wmma::mma_sync(c0, qa[kk], bb, c0);
        }
        wmma::store_matrix_sync(&Ss[wm*16][wn*16], c0, 36, wmma::mem_row_major);
        __syncthreads();

        // exp, accumulate l, write unnormalized P to gmem, rounded P to smem
        {
            float p[8];
            #pragma unroll
            for (int j = 0; j < 8; j++) {
                const float e = __expf(Ss[row][qd*8 + j]);
                p[j] = e;
                lsum += e;
                Ss[row][qd*8 + j] = wmma::__float_to_tf32(e);
            }
            float* wr = &w[(size_t)(m0 + row) * S_ + t0 + qd*8];
            *(float4*)wr       = make_float4(p[0], p[1], p[2], p[3]);
            *(float4*)(wr + 4) = make_float4(p[4], p[5], p[6], p[7]);
        }
        __syncthreads();

        // PV accumulate: attn[64,64] += P[64,32] @ V[32,64]
        #pragma unroll
        for (int kk = 0; kk < 32; kk += 8) {
            FragA a; wmma::load_matrix_sync(a, &Ss[wm*16][kk], 36);
            FragBr b0; wmma::load_matrix_sync(b0, &Vs[kk][wn*32], 68);
            wmma::mma_sync(pv0, a, b0, pv0);
            FragBr b1; wmma::load_matrix_sync(b1, &Vs[kk][wn*32 + 16], 68);
            wmma::mma_sync(pv1, a, b1, pv1);
        }
        __syncthreads();
    }

    // finalize 1/l per row (4 lanes of same row are consecutive)
    lsum += __shfl_xor_sync(0xffffffffu, lsum, 1);
    lsum += __shfl_xor_sync(0xffffffffu, lsum, 2);
    const float inv = 1.0f / lsum;
    if (qd == 0) {
        l_s[row] = inv;
        g_invl[(size_t)hb * S_ + m0 + row] = inv;
    }

    // stage PV, scale rows by 1/l, write concat layout [b, s, h*64 + d]
    wmma::store_matrix_sync(&Qs[wm*16][wn*32],      pv0, 68, wmma::mem_row_major);
    wmma::store_matrix_sync(&Qs[wm*16][wn*32 + 16], pv1, 68, wmma::mem_row_major);
    __syncthreads();
    #pragma unroll
    for (int i = 0; i < 4; i++) {
        const int vi = tid + i * 256;
        const int r = vi >> 4, c = (vi & 15) * 4;
        const float il = l_s[r];
        float4 s = *(float4*)&Qs[r][c];
        s.x *= il; s.y *= il; s.z *= il; s.w *= il;
        *(float4*)&g_concat[((size_t)(b * S_ + m0 + r)) * E_ + h * DH_ + c] = s;
    }
}

// ---------------------------------------------------------------------------
// K3: rescale weights in place by 1/l and accumulate electrode.
// grid (2, H*B, 8), block 256.  Each thread: 4 columns (float4), 256 rows.
// ---------------------------------------------------------------------------
__global__ void rescale_kernel(float* __restrict__ wts, float* __restrict__ elect) {
    const int hb = blockIdx.y;
    const int b = hb % B_;
    const int t = (blockIdx.x * 256 + threadIdx.x) * 4;
    const int s0 = blockIdx.z * 256;

    __shared__ float il[256];
    il[threadIdx.x] = g_invl[(size_t)hb * S_ + s0 + threadIdx.x];
    __syncthreads();

    float* wp = wts + (size_t)hb * S_ * S_ + (size_t)s0 * S_ + t;
    float4 acc = make_float4(0.f, 0.f, 0.f, 0.f);
    #pragma unroll 4
    for (int s = 0; s < 256; s++) {
        float4 vv = *(float4*)(wp + (size_t)s * S_);
        const float f = il[s];
        vv.x *= f; vv.y *= f; vv.z *= f; vv.w *= f;
        *(float4*)(wp + (size_t)s * S_) = vv;
        acc.x += vv.x; acc.y += vv.y; acc.z += vv.z; acc.w += vv.w;
    }
    const float sc = 1.0f / (H_ * S_);
    atomicAdd(&elect[b * S_ + t],     acc.x * sc);
    atomicAdd(&elect[b * S_ + t + 1], acc.y * sc);
    atomicAdd(&elect[b * S_ + t + 2], acc.z * sc);
    atomicAdd(&elect[b * S_ + t + 3], acc.w * sc);
}

// ---------------------------------------------------------------------------
// K4: O-projection (tf32, pre-rounded).  x[m,n] = sum_k concat[m,k]*Wo[n,k]+bo[n]
// grid (E/64, BS/64), block 256.  Tile 64x64, K-chunk 64.
// ---------------------------------------------------------------------------
__global__ void oproj_tc_kernel(const float* __restrict__ Wo, const float* __restrict__ bo,
                                float* __restrict__ x) {
    const int n0 = blockIdx.x * 64, m0 = blockIdx.y * 64;

    __shared__ float As[64][68];
    __shared__ float Bs[64][68];   // Bs[n][k]
    float (*St)[68] = As;

    const int tid  = threadIdx.x;
    const int warp = tid >> 5;
    const int wm = warp >> 1, wn = warp & 1;

    FragC c0, c1;
    wmma::fill_fragment(c0, 0.f);
    wmma::fill_fragment(c1, 0.f);

    for (int k0 = 0; k0 < E_; k0 += 64) {
        #pragma unroll
        for (int i = 0; i < 4; i++) {
            const int vi = tid + i * 256;
            const int r = vi >> 4, c = (vi & 15) * 4;
            *(float4*)&As[r][c] = tf4(*(const float4*)&g_concat[(size_t)(m0 + r) * E_ + k0 + c]);
            *(float4*)&Bs[r][c] = tf4(*(const float4*)&Wo[(size_t)(n0 + r) * E_ + k0 + c]);
        }
        __syncthreads();
        #pragma unroll
        for (int kk = 0; kk < 64; kk += 8) {
            FragA a; wmma::load_matrix_sync(a, &As[wm*16][kk], 68);
            FragBc b0; wmma::load_matrix_sync(b0, &Bs[wn*32][kk], 68);
            wmma::mma_sync(c0, a, b0, c0);
            FragBc b1; wmma::load_matrix_sync(b1, &Bs[wn*32 + 16][kk], 68);
            wmma::mma_sync(c1, a, b1, c1);
        }
        __syncthreads();
    }
    wmma::store_matrix_sync(&St[wm*16][wn*32],      c0, 68, wmma::mem_row_major);
    wmma::store_matrix_sync(&St[wm*16][wn*32 + 16], c1, 68, wmma::mem_row_major);
    __syncthreads();
    #pragma unroll
    for (int i = 0; i < 4; i++) {
        const int vi = tid + i * 256;
        const int r = vi >> 4, c = (vi & 15) * 4;
        float4 s = *(float4*)&St[r][c];
        s.x += bo[n0 + c]; s.y += bo[n0 + c + 1]; s.z += bo[n0 + c + 2]; s.w += bo[n0 + c + 3];
        *(float4*)&x[(size_t)(m0 + r) * E_ + n0 + c] = s;
    }
}

// ---------------------------------------------------------------------------
__global__ void zero_elect_kernel(float* __restrict__ elect) {
    const int i = blockIdx.x * blockDim.x + threadIdx.x;
    if (i < B_ * S_) elect[i] = 0.f;
}

// ---------------------------------------------------------------------------
extern "C" void kernel_launch(void* const* d_in, const int* in_sizes, int n_in,
                              void* d_out, int out_size) {
    const float* hs = (const float*)d_in[0];
    const float* Wq = (const float*)d_in[1];
    const float* bq = (const float*)d_in[2];
    const float* Wk = (const float*)d_in[3];
    const float* bk = (const float*)d_in[4];
    const float* Wv = (const float*)d_in[5];
    const float* bv = (const float*)d_in[6];
    const float* Wo = (const float*)d_in[7];
    const float* bo = (const float*)d_in[8];

    float* out   = (float*)d_out;
    float* x     = out;                                        // [B,S,E]
    float* wts   = out + (size_t)B_ * S_ * E_;                 // [H,B,S,S]
    float* elect = wts + (size_t)H_ * B_ * S_ * S_;            // [B,S]

    zero_elect_kernel<<<(B_*S_ + 255)/256, 256>>>(elect);
    qkv_tc_kernel<<<dim3(BS_/64, H_, 3), 256>>>(hs, Wq, bq, Wk, bk, Wv, bv);
    attn_fused_kernel<<<dim3(S_/64, H_*B_), 256>>>(wts);
    rescale_kernel<<<dim3(2, H_*B_, 8), 256>>>(wts, elect);
    oproj_tc_kernel<<<dim3(E_/64, BS_/64), 256>>>(Wo, bo, x);
}

// round 13
// speedup vs baseline: 2.5408x; 2.1467x over previous
#include <cuda_runtime.h>
#include <cuda_fp16.h>
#include <mma.h>

using namespace nvcuda;

#define B_  4
#define S_  2048
#define E_  1024
#define H_  16
#define DH_ 64
#define BS_ (B_*S_)   // 8192

// Scratch (allocation-free rule: __device__ globals) — all half: 2x less traffic
__device__ __half g_q[H_*BS_*DH_];       // Q pre-scaled by 1/8
__device__ __half g_k[H_*BS_*DH_];
__device__ __half g_v[H_*BS_*DH_];
__device__ __half g_concat[BS_*E_];      // [b,s, h*64+d]
__device__ float  g_invl[H_*BS_];        // per-row 1/l

typedef wmma::fragment<wmma::matrix_a, 16,16,16, __half, wmma::row_major> HFragA;
typedef wmma::fragment<wmma::matrix_b, 16,16,16, __half, wmma::col_major> HFragBc;
typedef wmma::fragment<wmma::matrix_b, 16,16,16, __half, wmma::row_major> HFragBr;
typedef wmma::fragment<wmma::accumulator, 16,16,16, float> HFragC;

__device__ __forceinline__ void st_half4(__half* dst, float4 v) {
    *(half2*)dst       = __floats2half2_rn(v.x, v.y);
    *(half2*)(dst + 2) = __floats2half2_rn(v.z, v.w);
}

// ---------------------------------------------------------------------------
// K1: fused QKV projection (fp16 HMMA, fp32 accum).
// out[h,m,d] = half((sum_e hs[m,e]*W[h,e,d] + b[h,d]) * out_scale)
// grid (BS/64, H, 3), block 256.  Tile 64x64, K-chunk 64.
// ---------------------------------------------------------------------------
__global__ void qkv_tc_kernel(const float* __restrict__ hs,
                              const float* __restrict__ Wq, const float* __restrict__ bq,
                              const float* __restrict__ Wk, const float* __restrict__ bk,
                              const float* __restrict__ Wv, const float* __restrict__ bv) {
    const int h = blockIdx.y;
    const float* W; const float* bias; __half* out; float out_scale;
    if (blockIdx.z == 0)      { W = Wq; bias = bq; out = g_q; out_scale = 0.125f; }
    else if (blockIdx.z == 1) { W = Wk; bias = bk; out = g_k; out_scale = 1.0f; }
    else                      { W = Wv; bias = bv; out = g_v; out_scale = 1.0f; }
    W    += (size_t)h * E_ * DH_;
    bias += h * DH_;
    out  += (size_t)h * BS_ * DH_;

    // phases: fp16 tiles As+Bs = 18432 B;  fp32 stage St = 17408 B  -> 18432 B
    __shared__ __align__(16) unsigned char smbuf[18432];
    __half (*As)[72] = (__half(*)[72])smbuf;                // 64x64 half (+pad) 9216 B
    __half (*Bs)[72] = (__half(*)[72])(smbuf + 9216);       // 64x64 half (+pad) 9216 B
    float  (*St)[68] = (float(*)[68])smbuf;                 // 64x68 fp32 stage (aliases)

    const int tid  = threadIdx.x;
    const int warp = tid >> 5;
    const int wm = warp >> 1, wn = warp & 1;
    const int m0 = blockIdx.x * 64;

    HFragC c0, c1;
    wmma::fill_fragment(c0, 0.f);
    wmma::fill_fragment(c1, 0.f);

    for (int k0 = 0; k0 < E_; k0 += 64) {
        #pragma unroll
        for (int i = 0; i < 4; i++) {
            const int vi = tid + i * 256;
            const int r = vi >> 4, c = (vi & 15) * 4;
            st_half4(&As[r][c], *(const float4*)&hs[(size_t)(m0 + r) * E_ + k0 + c]);
            st_half4(&Bs[r][c], *(const float4*)&W[(size_t)(k0 + r) * DH_ + c]);
        }
        __syncthreads();
        #pragma unroll
        for (int kk = 0; kk < 64; kk += 16) {
            HFragA a; wmma::load_matrix_sync(a, &As[wm*16][kk], 72);
            HFragBr b0; wmma::load_matrix_sync(b0, &Bs[kk][wn*32], 72);
            wmma::mma_sync(c0, a, b0, c0);
            HFragBr b1; wmma::load_matrix_sync(b1, &Bs[kk][wn*32 + 16], 72);
            wmma::mma_sync(c1, a, b1, c1);
        }
        __syncthreads();
    }
    wmma::store_matrix_sync(&St[wm*16][wn*32],      c0, 68, wmma::mem_row_major);
    wmma::store_matrix_sync(&St[wm*16][wn*32 + 16], c1, 68, wmma::mem_row_major);
    __syncthreads();
    #pragma unroll
    for (int i = 0; i < 4; i++) {
        const int vi = tid + i * 256;
        const int r = vi >> 4, c = (vi & 15) * 4;
        float4 s = *(float4*)&St[r][c];
        s.x = (s.x + bias[c])   * out_scale;
        s.y = (s.y + bias[c+1]) * out_scale;
        s.z = (s.z + bias[c+2]) * out_scale;
        s.w = (s.w + bias[c+3]) * out_scale;
        st_half4(&out[(size_t)(m0 + r) * DH_ + c], s);
    }
}

// ---------------------------------------------------------------------------
// K2: single-pass attention (deferred normalization), fp16 HMMA.
// Per block: 64 query rows of one (h,b).  Streams KV in tiles of 32.
// Writes UNNORMALIZED exp(S) (fp32) to weights, accumulates l in registers,
// accumulates PV unnormalized (fp32 accum), scales by 1/l at epilogue.
// ---------------------------------------------------------------------------
__global__ void attn_fused_kernel(float* __restrict__ wts) {
    const int hb = blockIdx.y;
    const int h = hb / B_, b = hb % B_;
    const int m0 = blockIdx.x * 64;
    const __half* q = g_q + ((size_t)h * BS_ + (size_t)b * S_) * DH_;
    const __half* k = g_k + ((size_t)h * BS_ + (size_t)b * S_) * DH_;
    const __half* v = g_v + ((size_t)h * BS_ + (size_t)b * S_) * DH_;
    float* w = wts + (size_t)hb * S_ * S_;

    // layout: [0,9216) Qs half[64][72] -> later Ss float[64][36] (9216 B)
    //         [9216,13824) Ks half[32][72]
    //         [13824,18432) Vs half[32][72]
    //         [18432,23552) Ps half[64][40]
    // epilogue: St float[64][68] (17408 B) aliases from 0
    __shared__ __align__(16) unsigned char smbuf[23552];
    __half (*Qs)[72] = (__half(*)[72])smbuf;
    float  (*Ss)[36] = (float(*)[36])smbuf;
    __half (*Ks)[72] = (__half(*)[72])(smbuf + 9216);
    __half (*Vs)[72] = (__half(*)[72])(smbuf + 13824);
    __half (*Ps)[40] = (__half(*)[40])(smbuf + 18432);
    float  (*St)[68] = (float(*)[68])smbuf;
    __shared__ float l_s[64];

    const int tid  = threadIdx.x;
    const int warp = tid >> 5;
    const int wm = warp >> 1, wn = warp & 1;

    // load Q tile (pre-scaled by 1/8, half) — plain copy
    #pragma unroll
    for (int i = 0; i < 4; i++) {
        const int vi = tid + i * 256;
        const int r = vi >> 4, c = (vi & 15) * 4;
        *(uint2*)&Qs[r][c] = *(const uint2*)&q[(size_t)(m0 + r) * DH_ + c];
    }
    __syncthreads();

    HFragA qa[4];
    #pragma unroll
    for (int kk = 0; kk < 4; kk++)
        wmma::load_matrix_sync(qa[kk], &Qs[wm*16][kk*16], 72);
    __syncthreads();   // Qs free -> Ss

    const int row = tid >> 2, qd = tid & 3;   // 64 rows x 4 lanes
    float lsum = 0.f;

    HFragC pv0, pv1;
    wmma::fill_fragment(pv0, 0.f);
    wmma::fill_fragment(pv1, 0.f);

    for (int t0 = 0; t0 < S_; t0 += 32) {
        #pragma unroll
        for (int i = 0; i < 2; i++) {
            const int vi = tid + i * 256;
            const int r = vi >> 4, c = (vi & 15) * 4;
            *(uint2*)&Ks[r][c] = *(const uint2*)&k[(size_t)(t0 + r) * DH_ + c];
            *(uint2*)&Vs[r][c] = *(const uint2*)&v[(size_t)(t0 + r) * DH_ + c];
        }
        __syncthreads();

        // S = Q K^T : 64x32, warp tile 16x16
        HFragC c0;
        wmma::fill_fragment(c0, 0.f);
        #pragma unroll
        for (int kk = 0; kk < 4; kk++) {
            HFragBc bb; wmma::load_matrix_sync(bb, &Ks[wn*16][kk*16], 72);
            wmma::mma_sync(c0, qa[kk], bb, c0);
        }
        wmma::store_matrix_sync(&Ss[wm*16][wn*16], c0, 36, wmma::mem_row_major);
        __syncthreads();

        // exp, accumulate l, write fp32 unnormalized P to gmem, half P to smem
        {
            float p[8];
            #pragma unroll
            for (int j = 0; j < 8; j++) {
                const float e = __expf(Ss[row][qd*8 + j]);
                p[j] = e;
                lsum += e;
                Ps[row][qd*8 + j] = __float2half_rn(e);
            }
            float* wr = &w[(size_t)(m0 + row) * S_ + t0 + qd*8];
            *(float4*)wr       = make_float4(p[0], p[1], p[2], p[3]);
            *(float4*)(wr + 4) = make_float4(p[4], p[5], p[6], p[7]);
        }
        __syncthreads();

        // PV accumulate: attn[64,64] += P[64,32] @ V[32,64]
        #pragma unroll
        for (int kk = 0; kk < 32; kk += 16) {
            HFragA a; wmma::load_matrix_sync(a, &Ps[wm*16][kk], 40);
            HFragBr b0; wmma::load_matrix_sync(b0, &Vs[kk][wn*32], 72);
            wmma::mma_sync(pv0, a, b0, pv0);
            HFragBr b1; wmma::load_matrix_sync(b1, &Vs[kk][wn*32 + 16], 72);
            wmma::mma_sync(pv1, a, b1, pv1);
        }
        __syncthreads();
    }

    // finalize 1/l per row (4 lanes of same row are consecutive)
    lsum += __shfl_xor_sync(0xffffffffu, lsum, 1);
    lsum += __shfl_xor_sync(0xffffffffu, lsum, 2);
    const float inv = 1.0f / lsum;
    if (qd == 0) {
        l_s[row] = inv;
        g_invl[(size_t)hb * S_ + m0 + row] = inv;
    }

    // stage PV, scale rows by 1/l, write half concat layout [b, s, h*64 + d]
    wmma::store_matrix_sync(&St[wm*16][wn*32],      pv0, 68, wmma::mem_row_major);
    wmma::store_matrix_sync(&St[wm*16][wn*32 + 16], pv1, 68, wmma::mem_row_major);
    __syncthreads();
    #pragma unroll
    for (int i = 0; i < 4; i++) {
        const int vi = tid + i * 256;
        const int r = vi >> 4, c = (vi & 15) * 4;
        const float il = l_s[r];
        float4 s = *(float4*)&St[r][c];
        s.x *= il; s.y *= il; s.z *= il; s.w *= il;
        st_half4(&g_concat[((size_t)(b * S_ + m0 + r)) * E_ + h * DH_ + c], s);
    }
}

// ---------------------------------------------------------------------------
// K3: rescale weights in place by 1/l and accumulate electrode.
// grid (2, H*B, 8), block 256.  Each thread: 4 columns (float4), 256 rows.
// ---------------------------------------------------------------------------
__global__ void rescale_kernel(float* __restrict__ wts, float* __restrict__ elect) {
    const int hb = blockIdx.y;
    const int b = hb % B_;
    const int t = (blockIdx.x * 256 + threadIdx.x) * 4;
    const int s0 = blockIdx.z * 256;

    __shared__ float il[256];
    il[threadIdx.x] = g_invl[(size_t)hb * S_ + s0 + threadIdx.x];
    __syncthreads();

    float* wp = wts + (size_t)hb * S_ * S_ + (size_t)s0 * S_ + t;
    float4 acc = make_float4(0.f, 0.f, 0.f, 0.f);
    #pragma unroll 4
    for (int s = 0; s < 256; s++) {
        float4 vv = *(float4*)(wp + (size_t)s * S_);
        const float f = il[s];
        vv.x *= f; vv.y *= f; vv.z *= f; vv.w *= f;
        *(float4*)(wp + (size_t)s * S_) = vv;
        acc.x += vv.x; acc.y += vv.y; acc.z += vv.z; acc.w += vv.w;
    }
    const float sc = 1.0f / (H_ * S_);
    atomicAdd(&elect[b * S_ + t],     acc.x * sc);
    atomicAdd(&elect[b * S_ + t + 1], acc.y * sc);
    atomicAdd(&elect[b * S_ + t + 2], acc.z * sc);
    atomicAdd(&elect[b * S_ + t + 3], acc.w * sc);
}

// ---------------------------------------------------------------------------
// K4: O-projection (fp16 HMMA).  x[m,n] = sum_k concat[m,k]*Wo[n,k] + bo[n]
// grid (E/64, BS/64), block 256.  Tile 64x64, K-chunk 64.
// ---------------------------------------------------------------------------
__global__ void oproj_tc_kernel(const float* __restrict__ Wo, const float* __restrict__ bo,
                                float* __restrict__ x) {
    const int n0 = blockIdx.x * 64, m0 = blockIdx.y * 64;

    __shared__ __align__(16) unsigned char smbuf[18432];
    __half (*As)[72] = (__half(*)[72])smbuf;                // 64x64 half [m][k]
    __half (*Bs)[72] = (__half(*)[72])(smbuf + 9216);       // 64x64 half [n][k]
    float  (*St)[68] = (float(*)[68])smbuf;                 // stage (aliases, 17408 B)

    const int tid  = threadIdx.x;
    const int warp = tid >> 5;
    const int wm = warp >> 1, wn = warp & 1;

    HFragC c0, c1;
    wmma::fill_fragment(c0, 0.f);
    wmma::fill_fragment(c1, 0.f);

    for (int k0 = 0; k0 < E_; k0 += 64) {
        #pragma unroll
        for (int i = 0; i < 4; i++) {
            const int vi = tid + i * 256;
            const int r = vi >> 4, c = (vi & 15) * 4;
            *(uint2*)&As[r][c] = *(const uint2*)&g_concat[(size_t)(m0 + r) * E_ + k0 + c];
            st_half4(&Bs[r][c], *(const float4*)&Wo[(size_t)(n0 + r) * E_ + k0 + c]);
        }
        __syncthreads();
        #pragma unroll
        for (int kk = 0; kk < 64; kk += 16) {
            HFragA a; wmma::load_matrix_sync(a, &As[wm*16][kk], 72);
            HFragBc b0; wmma::load_matrix_sync(b0, &Bs[wn*32][kk], 72);
            wmma::mma_sync(c0, a, b0, c0);
            HFragBc b1; wmma::load_matrix_sync(b1, &Bs[wn*32 + 16][kk], 72);
            wmma::mma_sync(c1, a, b1, c1);
        }
        __syncthreads();
    }
    wmma::store_matrix_sync(&St[wm*16][wn*32],      c0, 68, wmma::mem_row_major);
    wmma::store_matrix_sync(&St[wm*16][wn*32 + 16], c1, 68, wmma::mem_row_major);
    __syncthreads();
    #pragma unroll
    for (int i = 0; i < 4; i++) {
        const int vi = tid + i * 256;
        const int r = vi >> 4, c = (vi & 15) * 4;
        float4 s = *(float4*)&St[r][c];
        s.x += bo[n0 + c]; s.y += bo[n0 + c + 1]; s.z += bo[n0 + c + 2]; s.w += bo[n0 + c + 3];
        *(float4*)&x[(size_t)(m0 + r) * E_ + n0 + c] = s;
    }
}

// ---------------------------------------------------------------------------
__global__ void zero_elect_kernel(float* __restrict__ elect) {
    const int i = blockIdx.x * blockDim.x + threadIdx.x;
    if (i < B_ * S_) elect[i] = 0.f;
}

// ---------------------------------------------------------------------------
extern "C" void kernel_launch(void* const* d_in, const int* in_sizes, int n_in,
                              void* d_out, int out_size) {
    const float* hs = (const float*)d_in[0];
    const float* Wq = (const float*)d_in[1];
    const float* bq = (const float*)d_in[2];
    const float* Wk = (const float*)d_in[3];
    const float* bk = (const float*)d_in[4];
    const float* Wv = (const float*)d_in[5];
    const float* bv = (const float*)d_in[6];
    const float* Wo = (const float*)d_in[7];
    const float* bo = (const float*)d_in[8];

    float* out   = (float*)d_out;
    float* x     = out;                                        // [B,S,E]
    float* wts   = out + (size_t)B_ * S_ * E_;                 // [H,B,S,S]
    float* elect = wts + (size_t)H_ * B_ * S_ * S_;            // [B,S]

    zero_elect_kernel<<<(B_*S_ + 255)/256, 256>>>(elect);
    qkv_tc_kernel<<<dim3(BS_/64, H_, 3), 256>>>(hs, Wq, bq, Wk, bk, Wv, bv);
    attn_fused_kernel<<<dim3(S_/64, H_*B_), 256>>>(wts);
    rescale_kernel<<<dim3(2, H_*B_, 8), 256>>>(wts, elect);
    oproj_tc_kernel<<<dim3(E_/64, BS_/64), 256>>>(Wo, bo, x);
}

// round 15
// speedup vs baseline: 2.7118x; 1.0673x over previous
#include <cuda_runtime.h>
#include <cuda_fp16.h>
#include <mma.h>

using namespace nvcuda;

#define B_  4
#define S_  2048
#define E_  1024
#define H_  16
#define DH_ 64
#define BS_ (B_*S_)   // 8192

// Scratch (allocation-free rule: __device__ globals)
__device__ __half g_q[H_*BS_*DH_];       // Q pre-scaled by 1/8
__device__ __half g_k[H_*BS_*DH_];
__device__ __half g_v[H_*BS_*DH_];
__device__ __half g_concat[BS_*E_];      // [b,s, h*64+d]

typedef wmma::fragment<wmma::matrix_a, 16,16,16, __half, wmma::row_major> HFragA;
typedef wmma::fragment<wmma::matrix_b, 16,16,16, __half, wmma::col_major> HFragBc;
typedef wmma::fragment<wmma::matrix_b, 16,16,16, __half, wmma::row_major> HFragBr;
typedef wmma::fragment<wmma::accumulator, 16,16,16, float> HFragC;

__device__ __forceinline__ void st_half4(__half* dst, float4 v) {
    *(half2*)dst       = __floats2half2_rn(v.x, v.y);
    *(half2*)(dst + 2) = __floats2half2_rn(v.z, v.w);
}

// ---------------------------------------------------------------------------
// K1: merged QKV projection (fp16 HMMA).  One block computes the 64x64 q,k,v
// tiles for one (m-tile, head): hs tile loaded ONCE for all three outputs.
// grid (BS/64, H), block 256.  K-chunk 64.
// ---------------------------------------------------------------------------
__global__ void qkv_tc_kernel(const float* __restrict__ hs,
                              const float* __restrict__ Wq, const float* __restrict__ bq,
                              const float* __restrict__ Wk, const float* __restrict__ bk,
                              const float* __restrict__ Wv, const float* __restrict__ bv) {
    const int h  = blockIdx.y;
    const int m0 = blockIdx.x * 64;
    const float* Wz[3] = { Wq + (size_t)h * E_ * DH_,
                           Wk + (size_t)h * E_ * DH_,
                           Wv + (size_t)h * E_ * DH_ };
    const float* bz[3] = { bq + h * DH_, bk + h * DH_, bv + h * DH_ };
    __half* oz[3] = { g_q + (size_t)h * BS_ * DH_ + (size_t)m0 * DH_,
                      g_k + (size_t)h * BS_ * DH_ + (size_t)m0 * DH_,
                      g_v + (size_t)h * BS_ * DH_ + (size_t)m0 * DH_ };

    // [0,9216) As half[64][72]; [9216 + z*9216) Bs[z]; St float[64][68] aliases 0
    __shared__ __align__(16) unsigned char smbuf[36864];
    __half (*As)[72] = (__half(*)[72])smbuf;
    float  (*St)[68] = (float(*)[68])smbuf;

    const int tid  = threadIdx.x;
    const int warp = tid >> 5;
    const int wm = warp >> 1, wn = warp & 1;

    HFragC acc[3][2];
    #pragma unroll
    for (int z = 0; z < 3; z++) {
        wmma::fill_fragment(acc[z][0], 0.f);
        wmma::fill_fragment(acc[z][1], 0.f);
    }

    for (int k0 = 0; k0 < E_; k0 += 64) {
        #pragma unroll
        for (int i = 0; i < 4; i++) {
            const int vi = tid + i * 256;
            const int r = vi >> 4, c = (vi & 15) * 4;
            st_half4(&As[r][c], *(const float4*)&hs[(size_t)(m0 + r) * E_ + k0 + c]);
            #pragma unroll
            for (int z = 0; z < 3; z++) {
                __half (*Bs)[72] = (__half(*)[72])(smbuf + 9216 + z * 9216);
                st_half4(&Bs[r][c], *(const float4*)&Wz[z][(size_t)(k0 + r) * DH_ + c]);
            }
        }
        __syncthreads();
        #pragma unroll
        for (int kk = 0; kk < 64; kk += 16) {
            HFragA a; wmma::load_matrix_sync(a, &As[wm*16][kk], 72);
            #pragma unroll
            for (int z = 0; z < 3; z++) {
                __half (*Bs)[72] = (__half(*)[72])(smbuf + 9216 + z * 9216);
                HFragBr b0; wmma::load_matrix_sync(b0, &Bs[kk][wn*32], 72);
                wmma::mma_sync(acc[z][0], a, b0, acc[z][0]);
                HFragBr b1; wmma::load_matrix_sync(b1, &Bs[kk][wn*32 + 16], 72);
                wmma::mma_sync(acc[z][1], a, b1, acc[z][1]);
            }
        }
        __syncthreads();
    }
    #pragma unroll
    for (int z = 0; z < 3; z++) {
        const float out_scale = (z == 0) ? 0.125f : 1.0f;
        wmma::store_matrix_sync(&St[wm*16][wn*32],      acc[z][0], 68, wmma::mem_row_major);
        wmma::store_matrix_sync(&St[wm*16][wn*32 + 16], acc[z][1], 68, wmma::mem_row_major);
        __syncthreads();
        const float* bias = bz[z];
        #pragma unroll
        for (int i = 0; i < 4; i++) {
            const int vi = tid + i * 256;
            const int r = vi >> 4, c = (vi & 15) * 4;
            float4 s = *(float4*)&St[r][c];
            s.x = (s.x + bias[c])   * out_scale;
            s.y = (s.y + bias[c+1]) * out_scale;
            s.z = (s.z + bias[c+2]) * out_scale;
            s.w = (s.w + bias[c+3]) * out_scale;
            st_half4(&oz[z][(size_t)r * DH_ + c], s);
        }
        __syncthreads();
    }
}

// ---------------------------------------------------------------------------
// K2: two-pass attention (fp16 HMMA), NO rescale kernel needed.
// Pass 1: stream K, S = QK^T, row-sum of exp(S) -> 1/l.
// Pass 2: recompute S, write NORMALIZED exp(S)/l (fp32) to weights,
//         electrode column sums (atomics), PV accumulate (normalized).
// grid (S/64, H*B), block 256.
// ---------------------------------------------------------------------------
__global__ void attn_fused_kernel(float* __restrict__ wts, float* __restrict__ elect) {
    const int hb = blockIdx.y;
    const int h = hb / B_, b = hb % B_;
    const int m0 = blockIdx.x * 64;
    const __half* q = g_q + ((size_t)h * BS_ + (size_t)b * S_) * DH_;
    const __half* k = g_k + ((size_t)h * BS_ + (size_t)b * S_) * DH_;
    const __half* v = g_v + ((size_t)h * BS_ + (size_t)b * S_) * DH_;
    float* w = wts + (size_t)hb * S_ * S_;

    // [0,9216) Qs half[64][72] -> Ss float[64][36]
    // [9216,13824) Ks half[32][72]; [13824,18432) Vs half[32][72]
    // [18432,23552) Ps half[64][40]; epilogue St float[64][68] aliases 0
    __shared__ __align__(16) unsigned char smbuf[23552];
    __half (*Qs)[72] = (__half(*)[72])smbuf;
    float  (*Ss)[36] = (float(*)[36])smbuf;
    __half (*Ks)[72] = (__half(*)[72])(smbuf + 9216);
    __half (*Vs)[72] = (__half(*)[72])(smbuf + 13824);
    __half (*Ps)[40] = (__half(*)[40])(smbuf + 18432);
    float  (*St)[68] = (float(*)[68])smbuf;
    __shared__ float l_s[64];

    const int tid  = threadIdx.x;
    const int warp = tid >> 5;
    const int wm = warp >> 1, wn = warp & 1;

    // load Q tile (pre-scaled by 1/8)
    #pragma unroll
    for (int i = 0; i < 4; i++) {
        const int vi = tid + i * 256;
        const int r = vi >> 4, c = (vi & 15) * 4;
        *(uint2*)&Qs[r][c] = *(const uint2*)&q[(size_t)(m0 + r) * DH_ + c];
    }
    __syncthreads();

    HFragA qa[4];
    #pragma unroll
    for (int kk = 0; kk < 4; kk++)
        wmma::load_matrix_sync(qa[kk], &Qs[wm*16][kk*16], 72);
    __syncthreads();   // Qs free -> Ss

    const int row = tid >> 2, qd = tid & 3;   // 64 rows x 4 lanes
    float lsum = 0.f;

    // ===================== pass 1: row sums of exp(S) =====================
    for (int t0 = 0; t0 < S_; t0 += 32) {
        #pragma unroll
        for (int i = 0; i < 2; i++) {
            const int vi = tid + i * 256;
            const int r = vi >> 4, c = (vi & 15) * 4;
            *(uint2*)&Ks[r][c] = *(const uint2*)&k[(size_t)(t0 + r) * DH_ + c];
        }
        __syncthreads();

        HFragC c0;
        wmma::fill_fragment(c0, 0.f);
        #pragma unroll
        for (int kk = 0; kk < 4; kk++) {
            HFragBc bb; wmma::load_matrix_sync(bb, &Ks[wn*16][kk*16], 72);
            wmma::mma_sync(c0, qa[kk], bb, c0);
        }
        wmma::store_matrix_sync(&Ss[wm*16][wn*16], c0, 36, wmma::mem_row_major);
        __syncthreads();

        #pragma unroll
        for (int j = 0; j < 8; j++) lsum += __expf(Ss[row][qd*8 + j]);
        __syncthreads();
    }
    lsum += __shfl_xor_sync(0xffffffffu, lsum, 1);
    lsum += __shfl_xor_sync(0xffffffffu, lsum, 2);
    if (qd == 0) l_s[row] = 1.0f / lsum;
    __syncthreads();
    const float il = l_s[row];

    // ===================== pass 2: normalized P + electrode + PV ==========
    HFragC pv0, pv1;
    wmma::fill_fragment(pv0, 0.f);
    wmma::fill_fragment(pv1, 0.f);

    const float esc = 1.0f / (H_ * S_);

    for (int t0 = 0; t0 < S_; t0 += 32) {
        #pragma unroll
        for (int i = 0; i < 2; i++) {
            const int vi = tid + i * 256;
            const int r = vi >> 4, c = (vi & 15) * 4;
            *(uint2*)&Ks[r][c] = *(const uint2*)&k[(size_t)(t0 + r) * DH_ + c];
            *(uint2*)&Vs[r][c] = *(const uint2*)&v[(size_t)(t0 + r) * DH_ + c];
        }
        __syncthreads();

        HFragC c0;
        wmma::fill_fragment(c0, 0.f);
        #pragma unroll
        for (int kk = 0; kk < 4; kk++) {
            HFragBc bb; wmma::load_matrix_sync(bb, &Ks[wn*16][kk*16], 72);
            wmma::mma_sync(c0, qa[kk], bb, c0);
        }
        wmma::store_matrix_sync(&Ss[wm*16][wn*16], c0, 36, wmma::mem_row_major);
        __syncthreads();

        // normalized p: write fp32 to weights, half to Ps
        {
            float p[8];
            #pragma unroll
            for (int j = 0; j < 8; j++) {
                p[j] = __expf(Ss[row][qd*8 + j]) * il;
                Ps[row][qd*8 + j] = __float2half_rn(p[j]);
            }
            float* wr = &w[(size_t)(m0 + row) * S_ + t0 + qd*8];
            *(float4*)wr       = make_float4(p[0], p[1], p[2], p[3]);
            *(float4*)(wr + 4) = make_float4(p[4], p[5], p[6], p[7]);
        }
        __syncthreads();

        // PV accumulate: attn[64,64] += P[64,32] @ V[32,64]
        #pragma unroll
        for (int kk = 0; kk < 32; kk += 16) {
            HFragA a; wmma::load_matrix_sync(a, &Ps[wm*16][kk], 40);
            HFragBr b0; wmma::load_matrix_sync(b0, &Vs[kk][wn*32], 72);
            wmma::mma_sync(pv0, a, b0, pv0);
            HFragBr b1; wmma::load_matrix_sync(b1, &Vs[kk][wn*32 + 16], 72);
            wmma::mma_sync(pv1, a, b1, pv1);
        }

        // electrode: warp 0 sums columns of Ps (64 rows x 32 cols)
        if (tid < 32) {
            float s = 0.f;
            #pragma unroll 8
            for (int r = 0; r < 64; r++) s += __half2float(Ps[r][tid]);
            atomicAdd(&elect[b * S_ + t0 + tid], s * esc);
        }
        __syncthreads();
    }

    // epilogue: stage PV (already normalized), write concat [b, s, h*64 + d]
    wmma::store_matrix_sync(&St[wm*16][wn*32],      pv0, 68, wmma::mem_row_major);
    wmma::store_matrix_sync(&St[wm*16][wn*32 + 16], pv1, 68, wmma::mem_row_major);
    __syncthreads();
    #pragma unroll
    for (int i = 0; i < 4; i++) {
        const int vi = tid + i * 256;
        const int r = vi >> 4, c = (vi & 15) * 4;
        float4 s = *(float4*)&St[r][c];
        st_half4(&g_concat[((size_t)(b * S_ + m0 + r)) * E_ + h * DH_ + c], s);
    }
}

// ---------------------------------------------------------------------------
// K3: O-projection (fp16 HMMA).  x[m,n] = sum_k concat[m,k]*Wo[n,k] + bo[n]
// grid (E/64, BS/64), block 256.  Tile 64x64, K-chunk 64.
// ---------------------------------------------------------------------------
__global__ void oproj_tc_kernel(const float* __restrict__ Wo, const float* __restrict__ bo,
                                float* __restrict__ x) {
    const int n0 = blockIdx.x * 64, m0 = blockIdx.y * 64;

    __shared__ __align__(16) unsigned char smbuf[18432];
    __half (*As)[72] = (__half(*)[72])smbuf;                // 64x64 half [m][k]
    __half (*Bs)[72] = (__half(*)[72])(smbuf + 9216);       // 64x64 half [n][k]
    float  (*St)[68] = (float(*)[68])smbuf;                 // stage (aliases)

    const int tid  = threadIdx.x;
    const int warp = tid >> 5;
    const int wm = warp >> 1, wn = warp & 1;

    HFragC c0, c1;
    wmma::fill_fragment(c0, 0.f);
    wmma::fill_fragment(c1, 0.f);

    for (int k0 = 0; k0 < E_; k0 += 64) {
        #pragma unroll
        for (int i = 0; i < 4; i++) {
            const int vi = tid + i * 256;
            const int r = vi >> 4, c = (vi & 15) * 4;
            *(uint2*)&As[r][c] = *(const uint2*)&g_concat[(size_t)(m0 + r) * E_ + k0 + c];
            st_half4(&Bs[r][c], *(const float4*)&Wo[(size_t)(n0 + r) * E_ + k0 + c]);
        }
        __syncthreads();
        #pragma unroll
        for (int kk = 0; kk < 64; kk += 16) {
            HFragA a; wmma::load_matrix_sync(a, &As[wm*16][kk], 72);
            HFragBc b0; wmma::load_matrix_sync(b0, &Bs[wn*32][kk], 72);
            wmma::mma_sync(c0, a, b0, c0);
            HFragBc b1; wmma::load_matrix_sync(b1, &Bs[wn*32 + 16][kk], 72);
            wmma::mma_sync(c1, a, b1, c1);
        }
        __syncthreads();
    }
    wmma::store_matrix_sync(&St[wm*16][wn*32],      c0, 68, wmma::mem_row_major);
    wmma::store_matrix_sync(&St[wm*16][wn*32 + 16], c1, 68, wmma::mem_row_major);
    __syncthreads();
    #pragma unroll
    for (int i = 0; i < 4; i++) {
        const int vi = tid + i * 256;
        const int r = vi >> 4, c = (vi & 15) * 4;
        float4 s = *(float4*)&St[r][c];
        s.x += bo[n0 + c]; s.y += bo[n0 + c + 1]; s.z += bo[n0 + c + 2]; s.w += bo[n0 + c + 3];
        *(float4*)&x[(size_t)(m0 + r) * E_ + n0 + c] = s;
    }
}

// ---------------------------------------------------------------------------
__global__ void zero_elect_kernel(float* __restrict__ elect) {
    const int i = blockIdx.x * blockDim.x + threadIdx.x;
    if (i < B_ * S_) elect[i] = 0.f;
}

// ---------------------------------------------------------------------------
extern "C" void kernel_launch(void* const* d_in, const int* in_sizes, int n_in,
                              void* d_out, int out_size) {
    const float* hs = (const float*)d_in[0];
    const float* Wq = (const float*)d_in[1];
    const float* bq = (const float*)d_in[2];
    const float* Wk = (const float*)d_in[3];
    const float* bk = (const float*)d_in[4];
    const float* Wv = (const float*)d_in[5];
    const float* bv = (const float*)d_in[6];
    const float* Wo = (const float*)d_in[7];
    const float* bo = (const float*)d_in[8];

    float* out   = (float*)d_out;
    float* x     = out;                                        // [B,S,E]
    float* wts   = out + (size_t)B_ * S_ * E_;                 // [H,B,S,S]
    float* elect = wts + (size_t)H_ * B_ * S_ * S_;            // [B,S]

    zero_elect_kernel<<<(B_*S_ + 255)/256, 256>>>(elect);
    qkv_tc_kernel<<<dim3(BS_/64, H_), 256>>>(hs, Wq, bq, Wk, bk, Wv, bv);
    attn_fused_kernel<<<dim3(S_/64, H_*B_), 256>>>(wts, elect);
    oproj_tc_kernel<<<dim3(E_/64, BS_/64), 256>>>(Wo, bo, x);
}